// round 5
// baseline (speedup 1.0000x reference)
#include <cuda_runtime.h>
#include <cstdint>
#include <math.h>

typedef unsigned int u32;

// Fully-fused NeRF forward, tf32 mma.sync tensor cores.
// Trunk layers (L0..L6) use 3xTF32 split-precision (error ~fp32) because the
// sigma output is sensitive; L7 + color head use single-pass tf32 (color has
// 100x error margin through sigmoid).
// CTA = 128 points, 256 threads (8 warps, 2m x 4n). Warp tile 64x64.
// Activations kept in SMEM as full fp32; weights staged per-K-chunk as
// (hi, lo) tf32 pairs.

#define NRF_THREADS 256
#define NRF_TILE    128
#define NRF_HSTR    260   // h_s row stride (4 mod 32 -> conflict-free frags)
#define NRF_ESTR    44
#define NRF_DSTR    36
#define NRF_WS      260   // weight stage row stride
#define NRF_KC      16    // K rows staged per chunk (hi+lo pair)

__device__ __forceinline__ float to_tf32(float x) {
    u32 u;
    asm("cvt.rna.tf32.f32 %0, %1;" : "=r"(u) : "f"(x));
    return __uint_as_float(u);
}
__device__ __forceinline__ u32 to_tf32_bits(float x) {
    u32 u;
    asm("cvt.rna.tf32.f32 %0, %1;" : "=r"(u) : "f"(x));
    return u;
}

__device__ __forceinline__ void mma8(float* d, const u32* a, const u32* b) {
    asm volatile(
        "mma.sync.aligned.m16n8k8.row.col.f32.tf32.tf32.f32 "
        "{%0,%1,%2,%3}, {%4,%5,%6,%7}, {%8,%9}, {%0,%1,%2,%3};\n"
        : "+f"(d[0]), "+f"(d[1]), "+f"(d[2]), "+f"(d[3])
        : "r"(a[0]), "r"(a[1]), "r"(a[2]), "r"(a[3]),
          "r"(b[0]), "r"(b[1]));
}

// ---- 3xTF32 K-segment accumulation, 256 output cols (trunk) ----
__device__ __forceinline__ void accum3x_256(
    float acc[4][8][4],
    const float* __restrict__ Wg, int ldw, int co, int kwbase,
    const float* __restrict__ src, int sstr, int Kreal,
    float* __restrict__ w_hi, float* __restrict__ w_lo,
    int mbase, int n0, int tg, int tq, int tid)
{
    const int Kpad = (Kreal + 7) & ~7;
    for (int k0 = 0; k0 < Kpad; k0 += NRF_KC) {
        const int kc = (NRF_KC < Kpad - k0) ? NRF_KC : (Kpad - k0);
        __syncthreads();  // protect weight buffers from previous consumers
        for (int idx = tid; idx < kc * 256; idx += NRF_THREADS) {
            const int r = idx >> 8;
            const int c = idx & 255;
            const int kk = k0 + r;
            const float w = (kk < Kreal)
                ? Wg[(size_t)(kwbase + kk) * ldw + co + c] : 0.f;
            const float hi = to_tf32(w);
            w_hi[r * NRF_WS + c] = hi;
            w_lo[r * NRF_WS + c] = to_tf32(w - hi);
        }
        __syncthreads();
        for (int ks = 0; ks < kc; ks += 8) {
            u32 bh[8][2], bl[8][2];
            #pragma unroll
            for (int nt = 0; nt < 8; nt++) {
                const int off = (ks + tq) * NRF_WS + n0 + nt * 8 + tg;
                bh[nt][0] = __float_as_uint(w_hi[off]);
                bh[nt][1] = __float_as_uint(w_hi[off + 4 * NRF_WS]);
                bl[nt][0] = __float_as_uint(w_lo[off]);
                bl[nt][1] = __float_as_uint(w_lo[off + 4 * NRF_WS]);
            }
            const int kabs = k0 + ks;
            #pragma unroll
            for (int mt = 0; mt < 4; mt++) {
                const float* sp = src + (mbase + mt * 16 + tg) * sstr + kabs + tq;
                float a0 = sp[0];
                float a1 = sp[8 * sstr];
                float a2 = sp[4];
                float a3 = sp[8 * sstr + 4];
                u32 ah[4], al[4];
                ah[0] = to_tf32_bits(a0);
                ah[1] = to_tf32_bits(a1);
                ah[2] = to_tf32_bits(a2);
                ah[3] = to_tf32_bits(a3);
                al[0] = to_tf32_bits(a0 - __uint_as_float(ah[0]));
                al[1] = to_tf32_bits(a1 - __uint_as_float(ah[1]));
                al[2] = to_tf32_bits(a2 - __uint_as_float(ah[2]));
                al[3] = to_tf32_bits(a3 - __uint_as_float(ah[3]));
                #pragma unroll
                for (int nt = 0; nt < 8; nt++) {
                    mma8(acc[mt][nt], al, bh[nt]);   // Alo*Bhi
                    mma8(acc[mt][nt], ah, bl[nt]);   // Ahi*Blo
                    mma8(acc[mt][nt], ah, bh[nt]);   // Ahi*Bhi
                }
            }
        }
    }
}

// ---- single-pass tf32, 256 output cols (L7) ----
__device__ __forceinline__ void accum1x_256(
    float acc[4][8][4],
    const float* __restrict__ Wg, int ldw, int co, int kwbase,
    const float* __restrict__ src, int sstr, int Kreal,
    float* __restrict__ w_hi,
    int mbase, int n0, int tg, int tq, int tid)
{
    const int Kpad = (Kreal + 7) & ~7;
    for (int k0 = 0; k0 < Kpad; k0 += NRF_KC) {
        const int kc = (NRF_KC < Kpad - k0) ? NRF_KC : (Kpad - k0);
        __syncthreads();
        for (int idx = tid; idx < kc * 256; idx += NRF_THREADS) {
            const int r = idx >> 8;
            const int c = idx & 255;
            const int kk = k0 + r;
            w_hi[r * NRF_WS + c] = (kk < Kreal)
                ? to_tf32(Wg[(size_t)(kwbase + kk) * ldw + co + c]) : 0.f;
        }
        __syncthreads();
        for (int ks = 0; ks < kc; ks += 8) {
            u32 bfr[8][2];
            #pragma unroll
            for (int nt = 0; nt < 8; nt++) {
                const int off = (ks + tq) * NRF_WS + n0 + nt * 8 + tg;
                bfr[nt][0] = __float_as_uint(w_hi[off]);
                bfr[nt][1] = __float_as_uint(w_hi[off + 4 * NRF_WS]);
            }
            const int kabs = k0 + ks;
            #pragma unroll
            for (int mt = 0; mt < 4; mt++) {
                const float* sp = src + (mbase + mt * 16 + tg) * sstr + kabs + tq;
                u32 afr[4];
                afr[0] = to_tf32_bits(sp[0]);
                afr[1] = to_tf32_bits(sp[8 * sstr]);
                afr[2] = to_tf32_bits(sp[4]);
                afr[3] = to_tf32_bits(sp[8 * sstr + 4]);
                #pragma unroll
                for (int nt = 0; nt < 8; nt++)
                    mma8(acc[mt][nt], afr, bfr[nt]);
            }
        }
    }
}

// ---- single-pass tf32, 128 output cols (color head) ----
__device__ __forceinline__ void accum1x_128(
    float acc[4][4][4],
    const float* __restrict__ Wg, int kwbase,
    const float* __restrict__ src, int sstr, int Kreal,
    float* __restrict__ w_hi,
    int mbase, int n0, int tg, int tq, int tid)
{
    const int Kpad = (Kreal + 7) & ~7;
    for (int k0 = 0; k0 < Kpad; k0 += NRF_KC) {
        const int kc = (NRF_KC < Kpad - k0) ? NRF_KC : (Kpad - k0);
        __syncthreads();
        for (int idx = tid; idx < kc * 128; idx += NRF_THREADS) {
            const int r = idx >> 7;
            const int c = idx & 127;
            const int kk = k0 + r;
            w_hi[r * NRF_WS + c] = (kk < Kreal)
                ? to_tf32(Wg[(size_t)(kwbase + kk) * 128 + c]) : 0.f;
        }
        __syncthreads();
        for (int ks = 0; ks < kc; ks += 8) {
            u32 bfr[4][2];
            #pragma unroll
            for (int nt = 0; nt < 4; nt++) {
                const int off = (ks + tq) * NRF_WS + n0 + nt * 8 + tg;
                bfr[nt][0] = __float_as_uint(w_hi[off]);
                bfr[nt][1] = __float_as_uint(w_hi[off + 4 * NRF_WS]);
            }
            const int kabs = k0 + ks;
            #pragma unroll
            for (int mt = 0; mt < 4; mt++) {
                const float* sp = src + (mbase + mt * 16 + tg) * sstr + kabs + tq;
                u32 afr[4];
                afr[0] = to_tf32_bits(sp[0]);
                afr[1] = to_tf32_bits(sp[8 * sstr]);
                afr[2] = to_tf32_bits(sp[4]);
                afr[3] = to_tf32_bits(sp[8 * sstr + 4]);
                #pragma unroll
                for (int nt = 0; nt < 4; nt++)
                    mma8(acc[mt][nt], afr, bfr[nt]);
            }
        }
    }
}

// ---- Epilogues: bias + optional ReLU, write fp32 to SMEM ----
__device__ __forceinline__ void epilogue_256(
    float acc[4][8][4], const float* __restrict__ bg, int co,
    float* __restrict__ dst, bool relu,
    int mbase, int n0, int tg, int tq)
{
    __syncthreads();  // all reads of src complete before overwrite
    #pragma unroll
    for (int nt = 0; nt < 8; nt++) {
        const int c = n0 + nt * 8 + 2 * tq;
        const float b0v = bg[co + c];
        const float b1v = bg[co + c + 1];
        #pragma unroll
        for (int mt = 0; mt < 4; mt++) {
            float v0 = acc[mt][nt][0] + b0v;
            float v1 = acc[mt][nt][1] + b1v;
            float v2 = acc[mt][nt][2] + b0v;
            float v3 = acc[mt][nt][3] + b1v;
            if (relu) {
                v0 = fmaxf(v0, 0.f); v1 = fmaxf(v1, 0.f);
                v2 = fmaxf(v2, 0.f); v3 = fmaxf(v3, 0.f);
            }
            const int r = mbase + mt * 16 + tg;
            *(float2*)(dst + r * NRF_HSTR + c)       = make_float2(v0, v1);
            *(float2*)(dst + (r + 8) * NRF_HSTR + c) = make_float2(v2, v3);
        }
    }
    __syncthreads();
}

__device__ __forceinline__ void epilogue_128(
    float acc[4][4][4], const float* __restrict__ bg,
    float* __restrict__ dst,
    int mbase, int n0, int tg, int tq)
{
    __syncthreads();
    #pragma unroll
    for (int nt = 0; nt < 4; nt++) {
        const int c = n0 + nt * 8 + 2 * tq;
        const float b0v = bg[c];
        const float b1v = bg[c + 1];
        #pragma unroll
        for (int mt = 0; mt < 4; mt++) {
            float v0 = fmaxf(acc[mt][nt][0] + b0v, 0.f);
            float v1 = fmaxf(acc[mt][nt][1] + b1v, 0.f);
            float v2 = fmaxf(acc[mt][nt][2] + b0v, 0.f);
            float v3 = fmaxf(acc[mt][nt][3] + b1v, 0.f);
            const int r = mbase + mt * 16 + tg;
            *(float2*)(dst + r * NRF_HSTR + c)       = make_float2(v0, v1);
            *(float2*)(dst + (r + 8) * NRF_HSTR + c) = make_float2(v2, v3);
        }
    }
    __syncthreads();
}

__device__ __forceinline__ void zero_acc8(float acc[4][8][4]) {
    #pragma unroll
    for (int i = 0; i < 4; i++)
        #pragma unroll
        for (int j = 0; j < 8; j++)
            #pragma unroll
            for (int k = 0; k < 4; k++) acc[i][j][k] = 0.f;
}

__global__ void __launch_bounds__(NRF_THREADS, 1) nerf_tc_kernel(
    const float* __restrict__ pts, const float* __restrict__ dirs,
    const float* __restrict__ W0, const float* __restrict__ b0,
    const float* __restrict__ W1, const float* __restrict__ b1,
    const float* __restrict__ W2, const float* __restrict__ b2,
    const float* __restrict__ W3, const float* __restrict__ b3,
    const float* __restrict__ W4, const float* __restrict__ b4,
    const float* __restrict__ W5, const float* __restrict__ b5,
    const float* __restrict__ W6, const float* __restrict__ b6,
    const float* __restrict__ W7, const float* __restrict__ b7,
    const float* __restrict__ Wc, const float* __restrict__ bc,
    const float* __restrict__ Wo, const float* __restrict__ bo,
    float* __restrict__ out_color, float* __restrict__ out_sigma, int P)
{
    extern __shared__ float sm[];
    float* h_s  = sm;                            // [TILE][HSTR] activations (fp32)
    float* e_s  = h_s + NRF_TILE * NRF_HSTR;     // [TILE][ESTR] xyz embedding
    float* d_s  = e_s + NRF_TILE * NRF_ESTR;     // [TILE][DSTR] dir embedding
    float* w_hi = d_s + NRF_TILE * NRF_DSTR;     // [KC][WS] staged weights (hi)
    float* w_lo = w_hi + NRF_KC * NRF_WS;        // [KC][WS] staged weights (lo)

    const int tid  = threadIdx.x;
    const int warp = tid >> 5;
    const int lane = tid & 31;
    const int tg = lane >> 2;
    const int tq = lane & 3;
    const int mbase  = (warp >> 2) * 64;
    const int n0_256 = (warp & 3) * 64;
    const int n0_128 = (warp & 3) * 32;
    const int base = blockIdx.x * NRF_TILE;

    // ---- Harmonic embeddings (one thread per point), fp32 ----
    if (tid < NRF_TILE) {
        const int n = base + tid;
        const float x = pts[n * 3 + 0];
        const float y = pts[n * 3 + 1];
        const float z = pts[n * 3 + 2];
        float* ep = e_s + tid * NRF_ESTR;
        #pragma unroll
        for (int h = 0; h < 6; h++) {
            const float f = (float)(1 << h);
            float sx, cx, sy, cy, sz, cz;
            sincosf(x * f, &sx, &cx);
            sincosf(y * f, &sy, &cy);
            sincosf(z * f, &sz, &cz);
            ep[0  + h] = sx; ep[6  + h] = sy; ep[12 + h] = sz;
            ep[18 + h] = cx; ep[24 + h] = cy; ep[30 + h] = cz;
        }
        ep[36] = x; ep[37] = y; ep[38] = z;
        #pragma unroll
        for (int c = 39; c < NRF_ESTR; c++) ep[c] = 0.f;

        const int r = n / P;
        const float dx = dirs[r * 3 + 0];
        const float dy = dirs[r * 3 + 1];
        const float dz = dirs[r * 3 + 2];
        float* dp = d_s + tid * NRF_DSTR;
        #pragma unroll
        for (int h = 0; h < 4; h++) {
            const float f = (float)(1 << h);
            float sx, cx, sy, cy, sz, cz;
            sincosf(dx * f, &sx, &cx);
            sincosf(dy * f, &sy, &cy);
            sincosf(dz * f, &sz, &cz);
            dp[0  + h] = sx; dp[4  + h] = sy; dp[8  + h] = sz;
            dp[12 + h] = cx; dp[16 + h] = cy; dp[20 + h] = cz;
        }
        dp[24] = dx; dp[25] = dy; dp[26] = dz;
        #pragma unroll
        for (int c = 27; c < NRF_DSTR; c++) dp[c] = 0.f;
    }
    __syncthreads();

    float acc[4][8][4];

    // ---- L0: e(39) -> 256, ReLU (3xTF32) ----
    zero_acc8(acc);
    accum3x_256(acc, W0, 256, 0, 0, e_s, NRF_ESTR, 39, w_hi, w_lo, mbase, n0_256, tg, tq, tid);
    epilogue_256(acc, b0, 0, h_s, true, mbase, n0_256, tg, tq);

    // ---- L1..L4: 256 -> 256, ReLU (3xTF32) ----
    {
        const float* Ws[4] = {W1, W2, W3, W4};
        const float* bs[4] = {b1, b2, b3, b4};
        #pragma unroll 1
        for (int l = 0; l < 4; l++) {
            zero_acc8(acc);
            accum3x_256(acc, Ws[l], 256, 0, 0, h_s, NRF_HSTR, 256, w_hi, w_lo, mbase, n0_256, tg, tq, tid);
            epilogue_256(acc, bs[l], 0, h_s, true, mbase, n0_256, tg, tq);
        }
    }

    // ---- L5: [h(256), e(39)] -> 256, ReLU (3xTF32) ----
    zero_acc8(acc);
    accum3x_256(acc, W5, 256, 0, 0,   h_s, NRF_HSTR, 256, w_hi, w_lo, mbase, n0_256, tg, tq, tid);
    accum3x_256(acc, W5, 256, 0, 256, e_s, NRF_ESTR, 39,  w_hi, w_lo, mbase, n0_256, tg, tq, tid);
    epilogue_256(acc, b5, 0, h_s, true, mbase, n0_256, tg, tq);

    // ---- L6: 256 -> 256, ReLU (3xTF32) ----
    zero_acc8(acc);
    accum3x_256(acc, W6, 256, 0, 0, h_s, NRF_HSTR, 256, w_hi, w_lo, mbase, n0_256, tg, tq, tid);
    epilogue_256(acc, b6, 0, h_s, true, mbase, n0_256, tg, tq);

    // ---- Sigma: col 0 of layer 7, from fp32 h6 (fp32 SIMT, reads only) ----
    if (tid < NRF_TILE) {
        float s = b7[0];
        const float* hp = h_s + tid * NRF_HSTR;
        #pragma unroll 4
        for (int k = 0; k < 256; k++) s = fmaf(hp[k], W7[k * 257], s);
        out_sigma[base + tid] = fmaxf(s, 0.f);
    }

    // ---- L7 cols 1..256: 256 -> 256, no ReLU (single tf32) ----
    zero_acc8(acc);
    accum1x_256(acc, W7, 257, 1, 0, h_s, NRF_HSTR, 256, w_hi, mbase, n0_256, tg, tq, tid);
    epilogue_256(acc, b7, 1, h_s, false, mbase, n0_256, tg, tq);

    // ---- Color head: [h7(256), d(27)] -> 128, ReLU (single tf32) ----
    {
        float acc2[4][4][4];
        #pragma unroll
        for (int i = 0; i < 4; i++)
            #pragma unroll
            for (int j = 0; j < 4; j++)
                #pragma unroll
                for (int k = 0; k < 4; k++) acc2[i][j][k] = 0.f;
        accum1x_128(acc2, Wc, 0,   h_s, NRF_HSTR, 256, w_hi, mbase, n0_128, tg, tq, tid);
        accum1x_128(acc2, Wc, 256, d_s, NRF_DSTR, 27,  w_hi, mbase, n0_128, tg, tq, tid);
        epilogue_128(acc2, bc, h_s, mbase, n0_128, tg, tq);
    }

    // ---- Output: sigmoid(h @ Wo + bo), 3 cols per point (384 pairs) ----
    for (int idx = tid; idx < NRF_TILE * 3; idx += NRF_THREADS) {
        const int p = idx / 3;
        const int c = idx - p * 3;
        float s = bo[c];
        const float* hp = h_s + p * NRF_HSTR;
        #pragma unroll 4
        for (int k = 0; k < 128; k++) s = fmaf(hp[k], Wo[k * 3 + c], s);
        out_color[(base + p) * 3 + c] = 1.f / (1.f + expf(-s));
    }
}

extern "C" void kernel_launch(void* const* d_in, const int* in_sizes, int n_in,
                              void* d_out, int out_size)
{
    const float* pts  = (const float*)d_in[0];
    const float* dirs = (const float*)d_in[1];
    const float* W0 = (const float*)d_in[2];   const float* b0 = (const float*)d_in[3];
    const float* W1 = (const float*)d_in[4];   const float* b1 = (const float*)d_in[5];
    const float* W2 = (const float*)d_in[6];   const float* b2 = (const float*)d_in[7];
    const float* W3 = (const float*)d_in[8];   const float* b3 = (const float*)d_in[9];
    const float* W4 = (const float*)d_in[10];  const float* b4 = (const float*)d_in[11];
    const float* W5 = (const float*)d_in[12];  const float* b5 = (const float*)d_in[13];
    const float* W6 = (const float*)d_in[14];  const float* b6 = (const float*)d_in[15];
    const float* W7 = (const float*)d_in[16];  const float* b7 = (const float*)d_in[17];
    const float* Wc = (const float*)d_in[18];  const float* bc = (const float*)d_in[19];
    const float* Wo = (const float*)d_in[20];  const float* bo = (const float*)d_in[21];

    const int N = in_sizes[0] / 3;        // 131072 points
    const int R = in_sizes[1] / 3;        // 2048 rays
    const int P = N / R;                  // 64 samples per ray

    float* out_color = (float*)d_out;               // [N,3] first (tuple order)
    float* out_sigma = out_color + (size_t)N * 3;   // [N,1] after

    const int smem_bytes = (NRF_TILE * NRF_HSTR + NRF_TILE * NRF_ESTR +
                            NRF_TILE * NRF_DSTR + 2 * NRF_KC * NRF_WS)
                           * (int)sizeof(float);
    cudaFuncSetAttribute(nerf_tc_kernel,
                         cudaFuncAttributeMaxDynamicSharedMemorySize, smem_bytes);

    nerf_tc_kernel<<<N / NRF_TILE, NRF_THREADS, smem_bytes>>>(
        pts, dirs,
        W0, b0, W1, b1, W2, b2, W3, b3, W4, b4, W5, b5, W6, b6, W7, b7,
        Wc, bc, Wo, bo,
        out_color, out_sigma, P);
}

// round 6
// speedup vs baseline: 1.6873x; 1.6873x over previous
#include <cuda_runtime.h>
#include <cstdint>
#include <math.h>

typedef unsigned int u32;

// Fully-fused NeRF forward, tf32 mma.sync tensor cores, 3xTF32 trunk.
// R6: ping-pong weight staging overlapped with mma (register prefetch),
// raw-fp32 staging with on-the-fly hi/lo split, d_s folded into e_s.

#define NRF_THREADS 256
#define NRF_TILE    128
#define NRF_HSTR    260   // activation row stride (4 mod 32 -> conflict-free)
#define NRF_ESTR    44    // embedding row stride (xyz, later reused for dir)
#define NRF_WS      260   // weight stage row stride
#define NRF_KC      16    // K rows per chunk (= prefetch regs per thread)

__device__ __forceinline__ float to_tf32(float x) {
    u32 u;
    asm("cvt.rna.tf32.f32 %0, %1;" : "=r"(u) : "f"(x));
    return __uint_as_float(u);
}
__device__ __forceinline__ u32 to_tf32_bits(float x) {
    u32 u;
    asm("cvt.rna.tf32.f32 %0, %1;" : "=r"(u) : "f"(x));
    return u;
}

__device__ __forceinline__ void mma8(float* d, const u32* a, const u32* b) {
    asm volatile(
        "mma.sync.aligned.m16n8k8.row.col.f32.tf32.tf32.f32 "
        "{%0,%1,%2,%3}, {%4,%5,%6,%7}, {%8,%9}, {%0,%1,%2,%3};\n"
        : "+f"(d[0]), "+f"(d[1]), "+f"(d[2]), "+f"(d[3])
        : "r"(a[0]), "r"(a[1]), "r"(a[2]), "r"(a[3]),
          "r"(b[0]), "r"(b[1]));
}

// =====================================================================
// 3xTF32 K-segment accumulation, 256 output cols (trunk layers).
// Ping-pong staging: raw fp32 weights; hi/lo split at fragment load.
// Each thread stages column `tid` of KC rows per chunk.
// =====================================================================
__device__ __forceinline__ void accum3x_256(
    float acc[4][8][4],
    const float* __restrict__ Wg, int ldw, int co, int kwbase,
    const float* __restrict__ src, int sstr, int Kreal,
    float* __restrict__ wbuf0, float* __restrict__ wbuf1,
    int mbase, int n0, int tg, int tq, int tid)
{
    const int Kpad = (Kreal + 7) & ~7;
    const int nch  = (Kpad + NRF_KC - 1) / NRF_KC;

    // stage chunk 0
    #pragma unroll
    for (int j = 0; j < NRF_KC; j++) {
        const int kk = j;
        wbuf0[j * NRF_WS + tid] = (kk < Kreal)
            ? Wg[(size_t)(kwbase + kk) * ldw + co + tid] : 0.f;
    }
    __syncthreads();

    for (int ci = 0; ci < nch; ci++) {
        float* cur = (ci & 1) ? wbuf1 : wbuf0;
        float* nxt = (ci & 1) ? wbuf0 : wbuf1;
        const int k0 = ci * NRF_KC;
        const int kc = (NRF_KC < Kpad - k0) ? NRF_KC : (Kpad - k0);
        const bool have_next = (ci + 1 < nch);

        // prefetch next chunk into registers (overlaps with mma below)
        float pf[NRF_KC];
        if (have_next) {
            const int kb = k0 + NRF_KC;
            #pragma unroll
            for (int j = 0; j < NRF_KC; j++) {
                const int kk = kb + j;
                pf[j] = (kk < Kreal)
                    ? Wg[(size_t)(kwbase + kk) * ldw + co + tid] : 0.f;
            }
        }

        // compute on current buffer
        for (int ks = 0; ks < kc; ks += 8) {
            u32 bh[8][2], bl[8][2];
            #pragma unroll
            for (int nt = 0; nt < 8; nt++) {
                const int off = (ks + tq) * NRF_WS + n0 + nt * 8 + tg;
                const float w0 = cur[off];
                const float w1 = cur[off + 4 * NRF_WS];
                const float h0 = to_tf32(w0);
                const float h1 = to_tf32(w1);
                bh[nt][0] = __float_as_uint(h0);
                bh[nt][1] = __float_as_uint(h1);
                bl[nt][0] = to_tf32_bits(w0 - h0);
                bl[nt][1] = to_tf32_bits(w1 - h1);
            }
            const int kabs = k0 + ks;
            #pragma unroll
            for (int mt = 0; mt < 4; mt++) {
                const float* sp = src + (mbase + mt * 16 + tg) * sstr + kabs + tq;
                const float a0 = sp[0];
                const float a1 = sp[8 * sstr];
                const float a2 = sp[4];
                const float a3 = sp[8 * sstr + 4];
                u32 ah[4], al[4];
                ah[0] = to_tf32_bits(a0);
                ah[1] = to_tf32_bits(a1);
                ah[2] = to_tf32_bits(a2);
                ah[3] = to_tf32_bits(a3);
                al[0] = to_tf32_bits(a0 - __uint_as_float(ah[0]));
                al[1] = to_tf32_bits(a1 - __uint_as_float(ah[1]));
                al[2] = to_tf32_bits(a2 - __uint_as_float(ah[2]));
                al[3] = to_tf32_bits(a3 - __uint_as_float(ah[3]));
                #pragma unroll
                for (int nt = 0; nt < 8; nt++) {
                    mma8(acc[mt][nt], al, bh[nt]);   // Alo*Bhi
                    mma8(acc[mt][nt], ah, bl[nt]);   // Ahi*Blo
                    mma8(acc[mt][nt], ah, bh[nt]);   // Ahi*Bhi
                }
            }
        }

        // store prefetched chunk
        if (have_next) {
            #pragma unroll
            for (int j = 0; j < NRF_KC; j++)
                nxt[j * NRF_WS + tid] = pf[j];
        }
        __syncthreads();
    }
}

// ---- single-pass tf32, 256 output cols (L7) ----
__device__ __forceinline__ void accum1x_256(
    float acc[4][8][4],
    const float* __restrict__ Wg, int ldw, int co, int kwbase,
    const float* __restrict__ src, int sstr, int Kreal,
    float* __restrict__ wbuf0, float* __restrict__ wbuf1,
    int mbase, int n0, int tg, int tq, int tid)
{
    const int Kpad = (Kreal + 7) & ~7;
    const int nch  = (Kpad + NRF_KC - 1) / NRF_KC;

    #pragma unroll
    for (int j = 0; j < NRF_KC; j++) {
        const int kk = j;
        wbuf0[j * NRF_WS + tid] = (kk < Kreal)
            ? Wg[(size_t)(kwbase + kk) * ldw + co + tid] : 0.f;
    }
    __syncthreads();

    for (int ci = 0; ci < nch; ci++) {
        float* cur = (ci & 1) ? wbuf1 : wbuf0;
        float* nxt = (ci & 1) ? wbuf0 : wbuf1;
        const int k0 = ci * NRF_KC;
        const int kc = (NRF_KC < Kpad - k0) ? NRF_KC : (Kpad - k0);
        const bool have_next = (ci + 1 < nch);

        float pf[NRF_KC];
        if (have_next) {
            const int kb = k0 + NRF_KC;
            #pragma unroll
            for (int j = 0; j < NRF_KC; j++) {
                const int kk = kb + j;
                pf[j] = (kk < Kreal)
                    ? Wg[(size_t)(kwbase + kk) * ldw + co + tid] : 0.f;
            }
        }

        for (int ks = 0; ks < kc; ks += 8) {
            u32 bfr[8][2];
            #pragma unroll
            for (int nt = 0; nt < 8; nt++) {
                const int off = (ks + tq) * NRF_WS + n0 + nt * 8 + tg;
                bfr[nt][0] = to_tf32_bits(cur[off]);
                bfr[nt][1] = to_tf32_bits(cur[off + 4 * NRF_WS]);
            }
            const int kabs = k0 + ks;
            #pragma unroll
            for (int mt = 0; mt < 4; mt++) {
                const float* sp = src + (mbase + mt * 16 + tg) * sstr + kabs + tq;
                u32 afr[4];
                afr[0] = to_tf32_bits(sp[0]);
                afr[1] = to_tf32_bits(sp[8 * sstr]);
                afr[2] = to_tf32_bits(sp[4]);
                afr[3] = to_tf32_bits(sp[8 * sstr + 4]);
                #pragma unroll
                for (int nt = 0; nt < 8; nt++)
                    mma8(acc[mt][nt], afr, bfr[nt]);
            }
        }

        if (have_next) {
            #pragma unroll
            for (int j = 0; j < NRF_KC; j++)
                nxt[j * NRF_WS + tid] = pf[j];
        }
        __syncthreads();
    }
}

// ---- single-pass tf32, 128 output cols (color head) ----
__device__ __forceinline__ void accum1x_128(
    float acc[4][4][4],
    const float* __restrict__ Wg, int kwbase,
    const float* __restrict__ src, int sstr, int Kreal,
    float* __restrict__ wbuf0, float* __restrict__ wbuf1,
    int mbase, int n0, int tg, int tq, int tid)
{
    const int Kpad = (Kreal + 7) & ~7;
    const int nch  = (Kpad + NRF_KC - 1) / NRF_KC;
    // 128 cols: two threads per column slot -> thread handles col tid&127,
    // rows j in {0..KC-1}, split rows between tid<128 and tid>=128.
    const int ccol = tid & 127;
    const int rhalf = (tid >> 7) * (NRF_KC / 2);   // 0 or KC/2

    #pragma unroll
    for (int j = 0; j < NRF_KC / 2; j++) {
        const int r = rhalf + j;
        const int kk = r;
        wbuf0[r * NRF_WS + ccol] = (kk < Kreal)
            ? Wg[(size_t)(kwbase + kk) * 128 + ccol] : 0.f;
    }
    __syncthreads();

    for (int ci = 0; ci < nch; ci++) {
        float* cur = (ci & 1) ? wbuf1 : wbuf0;
        float* nxt = (ci & 1) ? wbuf0 : wbuf1;
        const int k0 = ci * NRF_KC;
        const int kc = (NRF_KC < Kpad - k0) ? NRF_KC : (Kpad - k0);
        const bool have_next = (ci + 1 < nch);

        float pf[NRF_KC / 2];
        if (have_next) {
            const int kb = k0 + NRF_KC;
            #pragma unroll
            for (int j = 0; j < NRF_KC / 2; j++) {
                const int kk = kb + rhalf + j;
                pf[j] = (kk < Kreal)
                    ? Wg[(size_t)(kwbase + kk) * 128 + ccol] : 0.f;
            }
        }

        for (int ks = 0; ks < kc; ks += 8) {
            u32 bfr[4][2];
            #pragma unroll
            for (int nt = 0; nt < 4; nt++) {
                const int off = (ks + tq) * NRF_WS + n0 + nt * 8 + tg;
                bfr[nt][0] = to_tf32_bits(cur[off]);
                bfr[nt][1] = to_tf32_bits(cur[off + 4 * NRF_WS]);
            }
            const int kabs = k0 + ks;
            #pragma unroll
            for (int mt = 0; mt < 4; mt++) {
                const float* sp = src + (mbase + mt * 16 + tg) * sstr + kabs + tq;
                u32 afr[4];
                afr[0] = to_tf32_bits(sp[0]);
                afr[1] = to_tf32_bits(sp[8 * sstr]);
                afr[2] = to_tf32_bits(sp[4]);
                afr[3] = to_tf32_bits(sp[8 * sstr + 4]);
                #pragma unroll
                for (int nt = 0; nt < 4; nt++)
                    mma8(acc[mt][nt], afr, bfr[nt]);
            }
        }

        if (have_next) {
            #pragma unroll
            for (int j = 0; j < NRF_KC / 2; j++)
                nxt[(rhalf + j) * NRF_WS + ccol] = pf[j];
        }
        __syncthreads();
    }
}

// ---- Epilogues: bias + optional ReLU, write fp32 to SMEM (no syncs;
//      hazards covered by the accum chunk-loop barriers) ----
__device__ __forceinline__ void epilogue_256(
    float acc[4][8][4], const float* __restrict__ bg, int co,
    float* __restrict__ dst, bool relu,
    int mbase, int n0, int tg, int tq)
{
    #pragma unroll
    for (int nt = 0; nt < 8; nt++) {
        const int c = n0 + nt * 8 + 2 * tq;
        const float b0v = bg[co + c];
        const float b1v = bg[co + c + 1];
        #pragma unroll
        for (int mt = 0; mt < 4; mt++) {
            float v0 = acc[mt][nt][0] + b0v;
            float v1 = acc[mt][nt][1] + b1v;
            float v2 = acc[mt][nt][2] + b0v;
            float v3 = acc[mt][nt][3] + b1v;
            if (relu) {
                v0 = fmaxf(v0, 0.f); v1 = fmaxf(v1, 0.f);
                v2 = fmaxf(v2, 0.f); v3 = fmaxf(v3, 0.f);
            }
            const int r = mbase + mt * 16 + tg;
            *(float2*)(dst + r * NRF_HSTR + c)       = make_float2(v0, v1);
            *(float2*)(dst + (r + 8) * NRF_HSTR + c) = make_float2(v2, v3);
        }
    }
}

__device__ __forceinline__ void epilogue_128(
    float acc[4][4][4], const float* __restrict__ bg,
    float* __restrict__ dst,
    int mbase, int n0, int tg, int tq)
{
    #pragma unroll
    for (int nt = 0; nt < 4; nt++) {
        const int c = n0 + nt * 8 + 2 * tq;
        const float b0v = bg[c];
        const float b1v = bg[c + 1];
        #pragma unroll
        for (int mt = 0; mt < 4; mt++) {
            float v0 = fmaxf(acc[mt][nt][0] + b0v, 0.f);
            float v1 = fmaxf(acc[mt][nt][1] + b1v, 0.f);
            float v2 = fmaxf(acc[mt][nt][2] + b0v, 0.f);
            float v3 = fmaxf(acc[mt][nt][3] + b1v, 0.f);
            const int r = mbase + mt * 16 + tg;
            *(float2*)(dst + r * NRF_HSTR + c)       = make_float2(v0, v1);
            *(float2*)(dst + (r + 8) * NRF_HSTR + c) = make_float2(v2, v3);
        }
    }
}

__device__ __forceinline__ void zero_acc8(float acc[4][8][4]) {
    #pragma unroll
    for (int i = 0; i < 4; i++)
        #pragma unroll
        for (int j = 0; j < 8; j++)
            #pragma unroll
            for (int k = 0; k < 4; k++) acc[i][j][k] = 0.f;
}

__global__ void __launch_bounds__(NRF_THREADS, 1) nerf_tc_kernel(
    const float* __restrict__ pts, const float* __restrict__ dirs,
    const float* __restrict__ W0, const float* __restrict__ b0,
    const float* __restrict__ W1, const float* __restrict__ b1,
    const float* __restrict__ W2, const float* __restrict__ b2,
    const float* __restrict__ W3, const float* __restrict__ b3,
    const float* __restrict__ W4, const float* __restrict__ b4,
    const float* __restrict__ W5, const float* __restrict__ b5,
    const float* __restrict__ W6, const float* __restrict__ b6,
    const float* __restrict__ W7, const float* __restrict__ b7,
    const float* __restrict__ Wc, const float* __restrict__ bc,
    const float* __restrict__ Wo, const float* __restrict__ bo,
    float* __restrict__ out_color, float* __restrict__ out_sigma, int P)
{
    extern __shared__ float sm[];
    float* h_s   = sm;                           // [TILE][HSTR] activations fp32
    float* e_s   = h_s + NRF_TILE * NRF_HSTR;    // [TILE][ESTR] xyz emb, later dir emb
    float* wbuf0 = e_s + NRF_TILE * NRF_ESTR;    // [KC][WS] stage buffer 0
    float* wbuf1 = wbuf0 + NRF_KC * NRF_WS;      // [KC][WS] stage buffer 1

    const int tid  = threadIdx.x;
    const int warp = tid >> 5;
    const int lane = tid & 31;
    const int tg = lane >> 2;
    const int tq = lane & 3;
    const int mbase  = (warp >> 2) * 64;
    const int n0_256 = (warp & 3) * 64;
    const int n0_128 = (warp & 3) * 32;
    const int base = blockIdx.x * NRF_TILE;

    // ---- xyz harmonic embedding (one thread per point), fp32 ----
    if (tid < NRF_TILE) {
        const int n = base + tid;
        const float x = pts[n * 3 + 0];
        const float y = pts[n * 3 + 1];
        const float z = pts[n * 3 + 2];
        float* ep = e_s + tid * NRF_ESTR;
        #pragma unroll
        for (int h = 0; h < 6; h++) {
            const float f = (float)(1 << h);
            float sx, cx, sy, cy, sz, cz;
            sincosf(x * f, &sx, &cx);
            sincosf(y * f, &sy, &cy);
            sincosf(z * f, &sz, &cz);
            ep[0  + h] = sx; ep[6  + h] = sy; ep[12 + h] = sz;
            ep[18 + h] = cx; ep[24 + h] = cy; ep[30 + h] = cz;
        }
        ep[36] = x; ep[37] = y; ep[38] = z;
        #pragma unroll
        for (int c = 39; c < NRF_ESTR; c++) ep[c] = 0.f;
    }
    // (no sync needed: accum3x_256's chunk-0 stage barrier orders e_s writes)

    float acc[4][8][4];

    // ---- L0: e(39) -> 256, ReLU (3xTF32) ----
    zero_acc8(acc);
    accum3x_256(acc, W0, 256, 0, 0, e_s, NRF_ESTR, 39, wbuf0, wbuf1, mbase, n0_256, tg, tq, tid);
    epilogue_256(acc, b0, 0, h_s, true, mbase, n0_256, tg, tq);

    // ---- L1..L4: 256 -> 256, ReLU (3xTF32) ----
    {
        const float* Ws[4] = {W1, W2, W3, W4};
        const float* bs[4] = {b1, b2, b3, b4};
        #pragma unroll 1
        for (int l = 0; l < 4; l++) {
            zero_acc8(acc);
            accum3x_256(acc, Ws[l], 256, 0, 0, h_s, NRF_HSTR, 256, wbuf0, wbuf1, mbase, n0_256, tg, tq, tid);
            epilogue_256(acc, bs[l], 0, h_s, true, mbase, n0_256, tg, tq);
        }
    }

    // ---- L5: [h(256), e(39)] -> 256, ReLU (3xTF32) ----
    zero_acc8(acc);
    accum3x_256(acc, W5, 256, 0, 0,   h_s, NRF_HSTR, 256, wbuf0, wbuf1, mbase, n0_256, tg, tq, tid);
    accum3x_256(acc, W5, 256, 0, 256, e_s, NRF_ESTR, 39,  wbuf0, wbuf1, mbase, n0_256, tg, tq, tid);
    epilogue_256(acc, b5, 0, h_s, true, mbase, n0_256, tg, tq);

    // ---- L6: 256 -> 256, ReLU (3xTF32) ----
    zero_acc8(acc);
    accum3x_256(acc, W6, 256, 0, 0, h_s, NRF_HSTR, 256, wbuf0, wbuf1, mbase, n0_256, tg, tq, tid);
    epilogue_256(acc, b6, 0, h_s, true, mbase, n0_256, tg, tq);

    __syncthreads();   // h6 fully written before sigma reads whole rows

    // ---- Sigma: col 0 of layer 7, from fp32 h6 (fp32 SIMT, reads only) ----
    if (tid < NRF_TILE) {
        float s = b7[0];
        const float* hp = h_s + tid * NRF_HSTR;
        #pragma unroll 4
        for (int k = 0; k < 256; k++) s = fmaf(hp[k], W7[k * 257], s);
        out_sigma[base + tid] = fmaxf(s, 0.f);
    }
    // (sigma reads complete before L7's epilogue: L7 accum's internal
    //  barriers order them)

    // ---- L7 cols 1..256: 256 -> 256, no ReLU (single tf32) ----
    zero_acc8(acc);
    accum1x_256(acc, W7, 257, 1, 0, h_s, NRF_HSTR, 256, wbuf0, wbuf1, mbase, n0_256, tg, tq, tid);
    epilogue_256(acc, b7, 1, h_s, false, mbase, n0_256, tg, tq);

    // ---- dir harmonic embedding into e_s (e dead after L5) ----
    if (tid < NRF_TILE) {
        const int n = base + tid;
        const int r = n / P;
        const float dx = dirs[r * 3 + 0];
        const float dy = dirs[r * 3 + 1];
        const float dz = dirs[r * 3 + 2];
        float* dp = e_s + tid * NRF_ESTR;
        #pragma unroll
        for (int h = 0; h < 4; h++) {
            const float f = (float)(1 << h);
            float sx, cx, sy, cy, sz, cz;
            sincosf(dx * f, &sx, &cx);
            sincosf(dy * f, &sy, &cy);
            sincosf(dz * f, &sz, &cz);
            dp[0  + h] = sx; dp[4  + h] = sy; dp[8  + h] = sz;
            dp[12 + h] = cx; dp[16 + h] = cy; dp[20 + h] = cz;
        }
        dp[24] = dx; dp[25] = dy; dp[26] = dz;
        #pragma unroll
        for (int c = 27; c < 32; c++) dp[c] = 0.f;   // zero pad to Kpad=32
    }
    // (ordered before use by head accum's stage barrier)

    // ---- Color head: [h7(256), d(27)] -> 128, ReLU (single tf32) ----
    {
        float acc2[4][4][4];
        #pragma unroll
        for (int i = 0; i < 4; i++)
            #pragma unroll
            for (int j = 0; j < 4; j++)
                #pragma unroll
                for (int k = 0; k < 4; k++) acc2[i][j][k] = 0.f;
        accum1x_128(acc2, Wc, 0,   h_s, NRF_HSTR, 256, wbuf0, wbuf1, mbase, n0_128, tg, tq, tid);
        accum1x_128(acc2, Wc, 256, e_s, NRF_ESTR, 27,  wbuf0, wbuf1, mbase, n0_128, tg, tq, tid);
        epilogue_128(acc2, bc, h_s, mbase, n0_128, tg, tq);
    }

    __syncthreads();   // head output fully written before final reads

    // ---- Output: sigmoid(h @ Wo + bo), 3 cols per point (384 pairs) ----
    for (int idx = tid; idx < NRF_TILE * 3; idx += NRF_THREADS) {
        const int p = idx / 3;
        const int c = idx - p * 3;
        float s = bo[c];
        const float* hp = h_s + p * NRF_HSTR;
        #pragma unroll 4
        for (int k = 0; k < 128; k++) s = fmaf(hp[k], Wo[k * 3 + c], s);
        out_color[(base + p) * 3 + c] = 1.f / (1.f + expf(-s));
    }
}

extern "C" void kernel_launch(void* const* d_in, const int* in_sizes, int n_in,
                              void* d_out, int out_size)
{
    const float* pts  = (const float*)d_in[0];
    const float* dirs = (const float*)d_in[1];
    const float* W0 = (const float*)d_in[2];   const float* b0 = (const float*)d_in[3];
    const float* W1 = (const float*)d_in[4];   const float* b1 = (const float*)d_in[5];
    const float* W2 = (const float*)d_in[6];   const float* b2 = (const float*)d_in[7];
    const float* W3 = (const float*)d_in[8];   const float* b3 = (const float*)d_in[9];
    const float* W4 = (const float*)d_in[10];  const float* b4 = (const float*)d_in[11];
    const float* W5 = (const float*)d_in[12];  const float* b5 = (const float*)d_in[13];
    const float* W6 = (const float*)d_in[14];  const float* b6 = (const float*)d_in[15];
    const float* W7 = (const float*)d_in[16];  const float* b7 = (const float*)d_in[17];
    const float* Wc = (const float*)d_in[18];  const float* bc = (const float*)d_in[19];
    const float* Wo = (const float*)d_in[20];  const float* bo = (const float*)d_in[21];

    const int N = in_sizes[0] / 3;        // 131072 points
    const int R = in_sizes[1] / 3;        // 2048 rays
    const int P = N / R;                  // 64 samples per ray

    float* out_color = (float*)d_out;               // [N,3] first (tuple order)
    float* out_sigma = out_color + (size_t)N * 3;   // [N,1] after

    const int smem_bytes = (NRF_TILE * NRF_HSTR + NRF_TILE * NRF_ESTR +
                            2 * NRF_KC * NRF_WS) * (int)sizeof(float);
    cudaFuncSetAttribute(nerf_tc_kernel,
                         cudaFuncAttributeMaxDynamicSharedMemorySize, smem_bytes);

    nerf_tc_kernel<<<N / NRF_TILE, NRF_THREADS, smem_bytes>>>(
        pts, dirs,
        W0, b0, W1, b1, W2, b2, W3, b3, W4, b4, W5, b5, W6, b6, W7, b7,
        Wc, bc, Wo, bo,
        out_color, out_sigma, P);
}